// round 9
// baseline (speedup 1.0000x reference)
#include <cuda_runtime.h>
#include <math.h>
#include <stdint.h>

// Problem constants
#define BB 64
#define CC 16
#define FF 2048
#define JT 25            // stored joints per feature row
#define SPB 4            // series per block
#define NPARTS 6         // 24 joints / 4
#define NT 256           // 8 warps
#define CAP 26           // candidate slots per thread

// smem layout (words)
#define SLOT_OFF 0
#define CNT_OFF  (CAP * 256)          // 6656
#define REC_OFF  (CNT_OFF + 256)      // 6912
#define HIST_OFF (REC_OFF + 384)      // 7296
#define QOUT_OFF (HIST_OFF + 8 * 256) // 9344
#define SMEM_WORDS (QOUT_OFF + 32)    // 9376
#define SMEM_BYTES (SMEM_WORDS * 4)   // 37504

__device__ float g_stat2[BB * CC * 16 * 12];   // (b, c, s, j)
__device__ float g_weff[5 * 16 * 16 * 12];     // (cls, c, s, j)

__device__ __forceinline__ unsigned f2key(float x) {
    unsigned b = __float_as_uint(x);
    return b ^ ((unsigned)(((int)b) >> 31) | 0x80000000u);
}
__device__ __forceinline__ float key2f(unsigned k) {
    unsigned u = (k & 0x80000000u) ? (k & 0x7fffffffu) : ~k;
    return __uint_as_float(u);
}

// ---------------------------------------------------------------------------
// 256-bin histogram rank search (warp-uniform r). Returns bin; updates r to
// rank-within-bin; outputs bin count.
// ---------------------------------------------------------------------------
__device__ __forceinline__ int warp_find_bin256(const unsigned* hist, int lane,
                                                int& r, int& bincount) {
    const unsigned full = 0xffffffffu;
    unsigned c[8]; unsigned run = 0;
#pragma unroll
    for (int t = 0; t < 8; t++) { c[t] = hist[lane * 8 + t]; run += c[t]; }
    unsigned inc = run;
#pragma unroll
    for (int d = 1; d < 32; d <<= 1) {
        unsigned v = __shfl_up_sync(full, inc, d);
        if (lane >= d) inc += v;
    }
    unsigned acc = inc - run;
    int bin = -1, newr = 0; unsigned bc = 0;
#pragma unroll
    for (int t = 0; t < 8; t++) {
        if (bin < 0 && (int)acc <= r && r < (int)(acc + c[t])) {
            bin = lane * 8 + t; newr = r - (int)acc; bc = c[t];
        }
        acc += c[t];
    }
    unsigned m = __ballot_sync(full, bin >= 0);
    int srcl = __ffs(m) - 1;
    bin  = __shfl_sync(full, bin, srcl);
    newr = __shfl_sync(full, newr, srcl);
    bc   = __shfl_sync(full, bc, srcl);
    r = newr; bincount = (int)bc;
    return bin;
}

// ---------------------------------------------------------------------------
// Fallback: exact rank-r key via 32-pass bisection over GMEM series (rare).
// col0 = pointer to element f=0 of the series; stride 25 floats.
// ---------------------------------------------------------------------------
__device__ unsigned gsel_gmem(const float* col0, int lane, int r) {
    const unsigned full = 0xffffffffu;
    unsigned Klo = 0u, Khi = 0xffffffffu;
#pragma unroll 1
    while (Klo < Khi) {
        unsigned mid = Klo + ((Khi - Klo) >> 1);
        int cle = 0;
        for (int i = 0; i < 64; i++)
            cle += (f2key(__ldg(col0 + (size_t)(i * 32 + lane) * JT)) <= mid);
#pragma unroll
        for (int d = 16; d; d >>= 1) cle += __shfl_xor_sync(full, cle, d);
        if (r < cle) Khi = mid; else Klo = mid + 1u;
    }
    return Klo;
}

// ---------------------------------------------------------------------------
// Kernel A: one block per (b,c,part). Fused GMEM load + moments + counts +
// window gather (all in LDG shadow); selection over per-thread slot lists.
// ---------------------------------------------------------------------------
__global__ __launch_bounds__(NT, 5)
void stats_kernel(const float* __restrict__ features,
                  const float* __restrict__ W2, const float* __restrict__ Wl) {
    extern __shared__ unsigned sm[];
    const unsigned full = 0xffffffffu;

    const int blk  = blockIdx.x;
    const int bc   = blk / NPARTS;
    const int part = blk - bc * NPARTS;
    const int tid  = threadIdx.x;
    const int lane = tid & 31;
    const int w    = tid >> 5;

    const float* base = features + (size_t)bc * (FF * JT) + part * 4;

    // window pivots (data ~N(0,1); GMEM bisection fallback covers the rest)
    const float P0 = -0.80f, P1 = -0.55f, P2 = -0.125f,
                P3 =  0.125f, P4 =  0.55f, P5 =  0.80f;

    // ---- fused load + scan + gather (thread owns joint jj, 32 f-values) ----
    const int jj   = tid & 3;
    const int fb   = tid >> 2;                  // 0..63
    const int sidx = (tid >> 2) + ((tid & 3) << 6);   // t + 64*jj
    float s1 = 0.f, s2 = 0.f, s3 = 0.f, s4 = 0.f;
    float mn = INFINITY, mx = -INFINITY;
    int c0 = 0, c1 = 0, c2 = 0, cnt = 0;
#pragma unroll 8
    for (int k = 0; k < 32; k++) {
        float x = __ldg(base + (size_t)(fb + 64 * k) * JT + jj);
        s1 += x;
        float x2 = x * x;
        s2 += x2; s3 += x2 * x; s4 += x2 * x2;
        mn = fminf(mn, x); mx = fmaxf(mx, x);
        bool b0 = x < P0, b1 = x < P1, b2 = x < P2,
             b3 = x < P3, b4 = x < P4, b5 = x < P5;
        c0 += b0; c1 += b2; c2 += b4;
        bool in = (b1 && !b0) || (b3 && !b2) || (b5 && !b4);
        if (in) {
            if (cnt < CAP) sm[SLOT_OFF + cnt * 256 + sidx] = __float_as_uint(x);
            cnt++;
        }
    }
    // reduce over the 8 lanes sharing jj (xor 4,8,16 preserves lane&3)
#pragma unroll
    for (int d = 4; d <= 16; d <<= 1) {
        s1 += __shfl_xor_sync(full, s1, d);
        s2 += __shfl_xor_sync(full, s2, d);
        s3 += __shfl_xor_sync(full, s3, d);
        s4 += __shfl_xor_sync(full, s4, d);
        mn = fminf(mn, __shfl_xor_sync(full, mn, d));
        mx = fmaxf(mx, __shfl_xor_sync(full, mx, d));
        c0 += __shfl_xor_sync(full, c0, d);
        c1 += __shfl_xor_sync(full, c1, d);
        c2 += __shfl_xor_sync(full, c2, d);
    }
    if (lane < 4) {     // lane == jj for these lanes
        unsigned* r = sm + REC_OFF + (w * 4 + lane) * 12;
        r[0] = __float_as_uint(s1); r[1] = __float_as_uint(s2);
        r[2] = __float_as_uint(s3); r[3] = __float_as_uint(s4);
        r[4] = __float_as_uint(mn); r[5] = __float_as_uint(mx);
        r[6] = (unsigned)c0; r[7] = (unsigned)c1; r[8] = (unsigned)c2;
    }
    sm[CNT_OFF + sidx] = (unsigned)cnt;
    __syncthreads();

    // ---- selection: 12 tasks (4 series x 3 windows) over 8 warps ----
    const float PL[3] = {-0.80f, -0.125f, 0.55f};
    const float PH[3] = {-0.55f,  0.125f, 0.80f};
    const int   R0[3] = {511, 1023, 1535};
    float* qout = reinterpret_cast<float*>(sm + QOUT_OFF);
    unsigned* hist = sm + HIST_OFF + w * 256;

#pragma unroll 1
    for (int pass = 0; pass < 2; pass++) {
        int t = (pass == 0) ? w : (w < 4 ? 8 + w : -1);
        if (t < 0) break;
        int ts = t / 3, v = t - ts * 3;
        float Plo = PL[v], Phi = PH[v];
        int R = R0[v];
        int need1 = (v != 1);

        // count below window (sum rec over 8 warps)
        int cb = (lane < 8) ? (int)sm[REC_OFF + (lane * 4 + ts) * 12 + 6 + v] : 0;
#pragma unroll
        for (int d = 1; d <= 4; d <<= 1) cb += __shfl_xor_sync(full, cb, d);
        cb = __shfl_sync(full, cb, 0);
        int lr = R - cb;

        // per-source-thread counts for this series
        int cg0 = (int)sm[CNT_OFF + 64 * ts + lane];
        int cg1 = (int)sm[CNT_OFF + 64 * ts + 32 + lane];
        int mc = max(cg0, cg1);
#pragma unroll
        for (int d = 16; d; d >>= 1) mc = max(mc, __shfl_xor_sync(full, mc, d));
        bool ovf = (mc > CAP);

        // pass A: window count + key min/max
        int cw = 0;
        unsigned kmn = 0xffffffffu, kmx = 0u;
        if (!ovf) {
            for (int k = 0; k < mc; k++) {
#pragma unroll
                for (int g = 0; g < 2; g++) {
                    int cg = g ? cg1 : cg0;
                    if (k < cg) {
                        float x = __uint_as_float(
                            sm[SLOT_OFF + k * 256 + 64 * ts + g * 32 + lane]);
                        if (x >= Plo && x < Phi) {
                            unsigned kk = f2key(x);
                            cw++; kmn = min(kmn, kk); kmx = max(kmx, kk);
                        }
                    }
                }
            }
#pragma unroll
            for (int d = 16; d; d >>= 1) {
                cw  += __shfl_xor_sync(full, cw, d);
                kmn = min(kmn, __shfl_xor_sync(full, kmn, d));
                kmx = max(kmx, __shfl_xor_sync(full, kmx, d));
            }
        }

        bool ok = !ovf && (lr >= 0) && ((lr + need1) < cw);
        float v0, v1 = 0.f;
        if (ok) {
            if (kmn == kmx) {
                v0 = key2f(kmn); v1 = v0;
            } else {
                // radix rounds: re-scan slots, no compaction
                unsigned prefix = 0u, pmask = 0u;
                unsigned diff = kmn ^ kmx;
                int hib = 31 - __clz(diff);
                int sh = hib > 7 ? hib - 7 : 0;
                int cc = cw, lrr = lr;
#pragma unroll 1
                for (int round = 0; round < 5; round++) {
#pragma unroll
                    for (int u = 0; u < 8; u++) hist[lane + u * 32] = 0u;
                    __syncwarp();
                    for (int k = 0; k < mc; k++) {
#pragma unroll
                        for (int g = 0; g < 2; g++) {
                            int cg = g ? cg1 : cg0;
                            if (k < cg) {
                                float x = __uint_as_float(
                                    sm[SLOT_OFF + k * 256 + 64 * ts + g * 32 + lane]);
                                if (x >= Plo && x < Phi) {
                                    unsigned kk = f2key(x);
                                    if ((kk & pmask) == prefix)
                                        atomicAdd(&hist[(kk >> sh) & 0xFFu], 1u);
                                }
                            }
                        }
                    }
                    __syncwarp();
                    int bcnt;
                    int b = warp_find_bin256(hist, lane, lrr, bcnt);
                    prefix |= (unsigned)b << sh;
                    pmask  |= 0xFFu << sh;
                    cc = bcnt;
                    __syncwarp();
                    if (cc <= 32 || sh == 0) break;
                    sh = (sh >= 8) ? sh - 8 : 0;
                }
                // final gather of matching keys (<=32 or all-identical)
                unsigned* scr = hist;   // hist dead now
                unsigned mna = 0xffffffffu;
                int pos = 0;
                for (int k = 0; k < mc; k++) {
#pragma unroll
                    for (int g = 0; g < 2; g++) {
                        int cg = g ? cg1 : cg0;
                        bool match = false; unsigned kk = 0u;
                        if (k < cg) {
                            float x = __uint_as_float(
                                sm[SLOT_OFF + k * 256 + 64 * ts + g * 32 + lane]);
                            if (x >= Plo && x < Phi) {
                                kk = f2key(x);
                                unsigned masked = kk & pmask;
                                if (masked == prefix) match = true;
                                else if (masked > prefix) mna = min(mna, kk);
                            }
                        }
                        unsigned m = __ballot_sync(full, match);
                        if (match) {
                            int p2 = pos + __popc(m & ((1u << lane) - 1u));
                            if (p2 < 32) scr[p2] = kk;
                        }
                        pos += __popc(m);
                    }
                }
#pragma unroll
                for (int d = 16; d; d >>= 1)
                    mna = min(mna, __shfl_xor_sync(full, mna, d));
                __syncwarp();
                unsigned k0, k1;
                if (cc <= 32) {
                    unsigned vv = (lane < cc) ? scr[lane] : 0xffffffffu;
#pragma unroll
                    for (int k2 = 2; k2 <= 32; k2 <<= 1)
#pragma unroll
                        for (int j = k2 >> 1; j; j >>= 1) {
                            unsigned o = __shfl_xor_sync(full, vv, j);
                            bool keepMin = ((lane & j) == 0) == ((lane & k2) == 0);
                            vv = keepMin ? min(vv, o) : max(vv, o);
                        }
                    k0 = __shfl_sync(full, vv, lrr);
                    unsigned k1n = __shfl_sync(full, vv, (lrr + 1) & 31);
                    k1 = (lrr + 1 < cc) ? k1n : mna;
                } else {
                    // duplicates: all matching keys identical
                    k0 = scr[0];
                    k1 = (lrr + 1 < cc) ? k0 : mna;
                }
                v0 = key2f(k0);
                if (need1) v1 = key2f(k1);
            }
        } else {
            const float* col0 = features + (size_t)bc * (FF * JT) + part * 4 + ts;
            v0 = key2f(gsel_gmem(col0, lane, R));
            if (need1) v1 = key2f(gsel_gmem(col0, lane, R + 1));
        }
        if (lane == 0) {
            float* qo = qout + ts * 8;
            if (v == 0) { qo[0] = v0; qo[1] = v1; }
            else if (v == 1) { qo[2] = v0; }
            else { qo[3] = v0; qo[4] = v1; }
        }
    }
    __syncthreads();

    // ---- finalize (warp 0, lanes 0..3 -> one series each) ----
    if (w == 0 && lane < SPB) {
        int ss = lane;
        float ts1 = 0.f, ts2 = 0.f, ts3 = 0.f, ts4 = 0.f;
        float tmn = INFINITY, tmx = -INFINITY;
#pragma unroll
        for (int w2 = 0; w2 < 8; w2++) {
            const unsigned* r = sm + REC_OFF + (w2 * 4 + ss) * 12;
            ts1 += __uint_as_float(r[0]); ts2 += __uint_as_float(r[1]);
            ts3 += __uint_as_float(r[2]); ts4 += __uint_as_float(r[3]);
            tmn = fminf(tmn, __uint_as_float(r[4]));
            tmx = fmaxf(tmx, __uint_as_float(r[5]));
        }
        const float* qo = qout + ss * 8;
        const float n = 2048.f;
        float mean = ts1 / n;
        float m2 = ts2 / n, m3 = ts3 / n, m4 = ts4 / n;
        float varp = m2 - mean * mean;
        float var1 = varp * (n / (n - 1.f));
        float sd = sqrtf(var1);
        float mu2 = mean * mean;
        float m4c = m4 - 4.f * mean * m3 + 6.f * mu2 * m2 - 3.f * mu2 * mu2;
        float kurt = m4c / (var1 * var1) - 3.f;
        float q25 = 0.25f * qo[0] + 0.75f * qo[1];   // pos 511.75
        float med = qo[2];                            // pos 1023
        float q75 = 0.75f * qo[3] + 0.25f * qo[4];   // pos 1535.25

        int jg = part * SPB + ss;
        int bse = (jg < 12) ? 0 : 8;
        int col = (jg < 12) ? jg : (jg - 12);
        float* o = g_stat2 + ((size_t)bc * 16 + bse) * 12 + col;
        o[0 * 12] = tmx;
        o[1 * 12] = q25;
        o[2 * 12] = med;
        o[3 * 12] = q75;
        o[4 * 12] = mean;
        o[5 * 12] = sd;
        o[6 * 12] = tmx - tmn;
        o[7 * 12] = kurt;
    }

    // ---- weff tail: blocks 0..119, threads 0..127 ----
    if (blk < 120 && tid < 128) {
        int idx = blk * 128 + tid;
        int j   = idx % 12;
        int sx  = (idx / 12) & 15;
        int cx  = (idx / 192) & 15;
        int cls = idx / 3072;
        float a = 0.f;
#pragma unroll 8
        for (int e = 0; e < 64; e++)
            a += __ldg(&Wl[cls * 1024 + e * 16 + sx]) *
                 __ldg(&W2[(e * 16 + cx) * 12 + j]);
        g_weff[idx] = a;
    }
}

// ---------------------------------------------------------------------------
// Kernel B: logits[b,cls] = dot(stat2[b], weff[cls]) + sum b2*Wl + bl
// ---------------------------------------------------------------------------
__global__ __launch_bounds__(128)
void logits_kernel(const float* __restrict__ Wl, const float* __restrict__ b2,
                   const float* __restrict__ bl, float* __restrict__ out) {
    __shared__ float part[4];
    const unsigned full = 0xffffffffu;
    int blk = blockIdx.x;
    int b = blk / 5, cls = blk - b * 5;
    int tid = threadIdx.x;
    const float* st = g_stat2 + (size_t)b * 3072;
    const float* wf = g_weff + (size_t)cls * 3072;
    float a = 0.f;
    for (int i = tid; i < 3072; i += 128) a += st[i] * wf[i];
    for (int k = tid; k < 1024; k += 128)
        a += __ldg(&b2[k >> 4]) * __ldg(&Wl[cls * 1024 + k]);
#pragma unroll
    for (int d = 16; d; d >>= 1) a += __shfl_xor_sync(full, a, d);
    if ((tid & 31) == 0) part[tid >> 5] = a;
    __syncthreads();
    if (tid == 0)
        out[b * 5 + cls] = part[0] + part[1] + part[2] + part[3] + bl[cls];
}

// ---------------------------------------------------------------------------
extern "C" void kernel_launch(void* const* d_in, const int* in_sizes, int n_in,
                              void* d_out, int out_size) {
    const float* features = (const float*)d_in[0];
    // d_in[1]=W1, d_in[2]=b1 : dead in the reference (result discarded)
    const float* W2 = (const float*)d_in[3];
    const float* b2 = (const float*)d_in[4];
    const float* Wl = (const float*)d_in[5];
    const float* bl = (const float*)d_in[6];
    float* out = (float*)d_out;

    cudaFuncSetAttribute(stats_kernel,
                         cudaFuncAttributeMaxDynamicSharedMemorySize,
                         SMEM_BYTES);

    stats_kernel<<<BB * CC * NPARTS, NT, SMEM_BYTES>>>(features, W2, Wl);
    logits_kernel<<<BB * 5, 128>>>(Wl, b2, bl, out);
}

// round 10
// speedup vs baseline: 1.0857x; 1.0857x over previous
#include <cuda_runtime.h>
#include <math.h>
#include <stdint.h>

// Problem constants
#define BB 64
#define CC 16
#define FF 2048
#define JT 25            // stored joints per feature row
#define SPB 4            // series per block
#define NPARTS 6         // 24 joints / 4
#define NT 256           // 8 warps: 2 per series
#define RS 2056          // padded row stride (words): mod 32 == 8
#define CAPH 320         // combined-candidate capacity per half-series

#define DATA_WORDS (SPB * RS)                 // 8224
#define CAND_OFF   DATA_WORDS                 // 8224
#define HIST_OFF   (CAND_OFF + 8 * CAPH)      // 10784
#define REC_OFF    (HIST_OFF + 8 * 128)       // 11808
#define QOUT_OFF   (REC_OFF + 8 * 16)         // 11936
#define SMEM_WORDS (QOUT_OFF + SPB * 8)       // 11968
#define SMEM_BYTES (SMEM_WORDS * 4)           // 47872 -> 4 blocks/SM

__device__ float g_stat2[BB * CC * 16 * 12];   // (b, c, s, j)
__device__ float g_weff[5 * 16 * 16 * 12];     // (cls, c, s, j)

__device__ __forceinline__ unsigned f2key(float x) {
    unsigned b = __float_as_uint(x);
    return b ^ ((unsigned)(((int)b) >> 31) | 0x80000000u);
}
__device__ __forceinline__ float key2f(unsigned k) {
    unsigned u = (k & 0x80000000u) ? (k & 0x7fffffffu) : ~k;
    return __uint_as_float(u);
}

// ---------------------------------------------------------------------------
// 128-bin histogram rank search (warp-uniform r). Returns bin; updates r to
// rank-within-bin; outputs bin count.
// ---------------------------------------------------------------------------
__device__ __forceinline__ int warp_find_bin128(const unsigned* hist, int lane,
                                                int& r, int& bincount) {
    const unsigned full = 0xffffffffu;
    unsigned c[4]; unsigned run = 0;
#pragma unroll
    for (int t = 0; t < 4; t++) { c[t] = hist[lane * 4 + t]; run += c[t]; }
    unsigned inc = run;
#pragma unroll
    for (int d = 1; d < 32; d <<= 1) {
        unsigned v = __shfl_up_sync(full, inc, d);
        if (lane >= d) inc += v;
    }
    unsigned acc = inc - run;
    int bin = -1, newr = 0; unsigned bc = 0;
#pragma unroll
    for (int t = 0; t < 4; t++) {
        if (bin < 0 && (int)acc <= r && r < (int)(acc + c[t])) {
            bin = lane * 4 + t; newr = r - (int)acc; bc = c[t];
        }
        acc += c[t];
    }
    unsigned m = __ballot_sync(full, bin >= 0);
    int srcl = __ffs(m) - 1;
    bin  = __shfl_sync(full, bin, srcl);
    newr = __shfl_sync(full, newr, srcl);
    bc   = __shfl_sync(full, bc, srcl);
    r = newr; bincount = (int)bc;
    return bin;
}

// ---------------------------------------------------------------------------
// Correctness fallback: exact rank-r key via bisection over the intact row.
// ---------------------------------------------------------------------------
__device__ unsigned generic_select_row(const unsigned* row, int lane, int r) {
    const unsigned full = 0xffffffffu;
    unsigned Klo = 0u, Khi = 0xffffffffu;
#pragma unroll 1
    while (Klo < Khi) {
        unsigned mid = Klo + ((Khi - Klo) >> 1);
        int cle = 0;
        for (int i = 0; i < 64; i++)
            cle += (f2key(__uint_as_float(row[i * 32 + lane])) <= mid);
#pragma unroll
        for (int d = 16; d; d >>= 1) cle += __shfl_xor_sync(full, cle, d);
        if (r < cle) Khi = mid; else Klo = mid + 1u;
    }
    return Klo;
}

// ---------------------------------------------------------------------------
// Kernel A: one block per (b,c,part); 4 series, 2 warps per series.
// ---------------------------------------------------------------------------
__global__ __launch_bounds__(NT, 4)
void stats_kernel(const float* __restrict__ features,
                  const float* __restrict__ W2, const float* __restrict__ Wl) {
    extern __shared__ unsigned sm[];
    const unsigned full = 0xffffffffu;

    const int blk  = blockIdx.x;
    const int bc   = blk / NPARTS;
    const int part = blk - bc * NPARTS;       // 0..5 -> joints part*4 .. +3
    const int tid  = threadIdx.x;

    const float* src = features + (size_t)bc * (FF * JT) + part * 4;
    float* smf = reinterpret_cast<float*>(sm);

    // ---- phase 1: load 4 joints, transpose to rows (conflict-free) ----
    {
        int jj = tid & 3;
        int f  = tid >> 2;                    // 0..63
#pragma unroll 8
        for (int k = 0; k < 32; k++, f += 64)
            smf[jj * RS + f] = __ldg(src + f * JT + jj);
    }
    __syncthreads();

    const int w    = tid >> 5;
    const int lane = tid & 31;
    const int s    = w >> 1;                  // series 0..3
    const int h    = w & 1;                   // half 0..1

    // window pivots (data ~N(0,1); smem bisection fallback covers the rest)
    const float P0 = -0.80f, P1 = -0.55f, P2 = -0.125f,
                P3 =  0.125f, P4 =  0.55f, P5 =  0.80f;

    // ---- phase 2: fused half-scan: moments + counts + combined gather ----
    const unsigned* rowh = sm + s * RS + h * 1024;
    unsigned* cand = sm + CAND_OFF + w * CAPH;
    float s1 = 0.f, s2 = 0.f, s3 = 0.f, s4 = 0.f;
    float mn = INFINITY, mx = -INFINITY;
    int c0 = 0, c1 = 0, c2 = 0;
    int p = 0;                                 // combined window fill
#pragma unroll 4
    for (int i = 0; i < 32; i++) {
        float x = __uint_as_float(rowh[i * 32 + lane]);
        s1 += x;
        float x2 = x * x;
        s2 += x2; s3 += x2 * x; s4 += x2 * x2;
        mn = fminf(mn, x); mx = fmaxf(mx, x);
        bool b0 = x < P0, b1 = x < P1, b2 = x < P2,
             b3 = x < P3, b4 = x < P4, b5 = x < P5;
        c0 += b0; c1 += b2; c2 += b4;
        bool in = (b1 && !b0) || (b3 && !b2) || (b5 && !b4);
        unsigned m = __ballot_sync(full, in);
        if (in) {
            int pos = p + __popc(m & ((1u << lane) - 1u));
            if (pos < CAPH) cand[pos] = __float_as_uint(x);
        }
        p += __popc(m);
    }
#pragma unroll
    for (int d = 16; d; d >>= 1) {
        s1 += __shfl_xor_sync(full, s1, d);
        s2 += __shfl_xor_sync(full, s2, d);
        s3 += __shfl_xor_sync(full, s3, d);
        s4 += __shfl_xor_sync(full, s4, d);
        mn = fminf(mn, __shfl_xor_sync(full, mn, d));
        mx = fmaxf(mx, __shfl_xor_sync(full, mx, d));
        c0 += __shfl_xor_sync(full, c0, d);
        c1 += __shfl_xor_sync(full, c1, d);
        c2 += __shfl_xor_sync(full, c2, d);
    }
    unsigned* rec = sm + REC_OFF + w * 16;
    if (lane == 0) {
        rec[0] = __float_as_uint(s1); rec[1] = __float_as_uint(s2);
        rec[2] = __float_as_uint(s3); rec[3] = __float_as_uint(s4);
        rec[4] = __float_as_uint(mn); rec[5] = __float_as_uint(mx);
        rec[6] = (unsigned)c0; rec[7] = (unsigned)c1; rec[8] = (unsigned)c2;
        rec[9] = (unsigned)p;
    }
    __syncthreads();

    // ---- phase 3: 12 selection tasks over 8 warps ----
    const float PL[3] = {-0.80f, -0.125f, 0.55f};
    const float PH[3] = {-0.55f,  0.125f, 0.80f};
    const int   R0[3] = {511, 1023, 1535};

    unsigned* hist = sm + HIST_OFF + w * 128;
    float* qout = reinterpret_cast<float*>(sm + QOUT_OFF);

#pragma unroll 1
    for (int pass = 0; pass < 2; pass++) {
        int t = (pass == 0) ? w : (w < 4 ? 8 + w : -1);
        if (t < 0) break;
        int ts = t / 3, v = t - ts * 3;
        const unsigned* r0 = sm + REC_OFF + (2 * ts) * 16;
        const unsigned* r1 = r0 + 16;
        int clow = (int)r0[6 + v] + (int)r1[6 + v];
        int pa = (int)r0[9], pb = (int)r1[9];
        int lr = R0[v] - clow;
        int need1 = (v != 1);
        float Plo = PL[v], Phi = PH[v];
        const unsigned* cb0 = sm + CAND_OFF + (2 * ts) * CAPH;
        const unsigned* cb1 = cb0 + CAPH;
        bool overflow = (pa > CAPH) || (pb > CAPH);

        // pass A: window count + key min/max over both halves' candidates
        int cw = 0;
        unsigned kmn = 0xffffffffu, kmx = 0u;
        if (!overflow) {
#pragma unroll 1
            for (int seg = 0; seg < 2; seg++) {
                const unsigned* cb = seg ? cb1 : cb0;
                int pc = seg ? pb : pa;
                for (int idx = lane; idx < pc; idx += 32) {
                    float x = __uint_as_float(cb[idx]);
                    if (x >= Plo && x < Phi) {
                        unsigned kk = f2key(x);
                        cw++; kmn = min(kmn, kk); kmx = max(kmx, kk);
                    }
                }
            }
#pragma unroll
            for (int d = 16; d; d >>= 1) {
                cw  += __shfl_xor_sync(full, cw, d);
                kmn = min(kmn, __shfl_xor_sync(full, kmn, d));
                kmx = max(kmx, __shfl_xor_sync(full, kmx, d));
            }
            __syncwarp();
        }

        bool ok = !overflow && (lr >= 0) && ((lr + need1) < cw);
        float v0, v1 = 0.f;
        if (ok) {
            unsigned k0, k1;
            if (kmn == kmx) {
                k0 = kmn; k1 = kmn;
            } else {
                // adaptive 7-bit radix rounds over the candidate arrays
                unsigned prefix = 0u, pmask = 0u;
                unsigned diff = kmn ^ kmx;
                int hib = 31 - __clz(diff);
                int sh = hib > 6 ? hib - 6 : 0;
                int cc = cw, lrr = lr;
#pragma unroll 1
                for (int round = 0; round < 5; round++) {
#pragma unroll
                    for (int u = 0; u < 4; u++) hist[lane + u * 32] = 0u;
                    __syncwarp();
#pragma unroll 1
                    for (int seg = 0; seg < 2; seg++) {
                        const unsigned* cb = seg ? cb1 : cb0;
                        int pc = seg ? pb : pa;
                        for (int idx = lane; idx < pc; idx += 32) {
                            float x = __uint_as_float(cb[idx]);
                            if (x >= Plo && x < Phi) {
                                unsigned kk = f2key(x);
                                if ((kk & pmask) == prefix)
                                    atomicAdd(&hist[(kk >> sh) & 0x7Fu], 1u);
                            }
                        }
                    }
                    __syncwarp();
                    int bcnt;
                    int b = warp_find_bin128(hist, lane, lrr, bcnt);
                    prefix |= (unsigned)b << sh;
                    pmask  |= 0x7Fu << sh;
                    cc = bcnt;
                    __syncwarp();
                    if (cc <= 32 || sh == 0) break;
                    sh = (sh >= 7) ? sh - 7 : 0;
                }
                // final gather of matching keys (<=32, or all-identical)
                unsigned* scr = hist;   // hist dead now
                unsigned mna = 0xffffffffu;
                int pos = 0;
#pragma unroll 1
                for (int seg = 0; seg < 2; seg++) {
                    const unsigned* cb = seg ? cb1 : cb0;
                    int pc = seg ? pb : pa;
                    for (int base = 0; base < pc; base += 32) {
                        int idx = base + lane;
                        bool match = false; unsigned kk = 0u;
                        if (idx < pc) {
                            float x = __uint_as_float(cb[idx]);
                            if (x >= Plo && x < Phi) {
                                kk = f2key(x);
                                unsigned masked = kk & pmask;
                                if (masked == prefix) match = true;
                                else if (masked > prefix) mna = min(mna, kk);
                            }
                        }
                        unsigned m = __ballot_sync(full, match);
                        if (match) {
                            int p2 = pos + __popc(m & ((1u << lane) - 1u));
                            if (p2 < 32) scr[p2] = kk;
                        }
                        pos += __popc(m);
                    }
                }
#pragma unroll
                for (int d = 16; d; d >>= 1)
                    mna = min(mna, __shfl_xor_sync(full, mna, d));
                __syncwarp();
                if (cc <= 32) {
                    unsigned vv = (lane < cc) ? scr[lane] : 0xffffffffu;
#pragma unroll
                    for (int k2 = 2; k2 <= 32; k2 <<= 1)
#pragma unroll
                        for (int j = k2 >> 1; j; j >>= 1) {
                            unsigned o = __shfl_xor_sync(full, vv, j);
                            bool keepMin = ((lane & j) == 0) == ((lane & k2) == 0);
                            vv = keepMin ? min(vv, o) : max(vv, o);
                        }
                    k0 = __shfl_sync(full, vv, lrr);
                    unsigned k1n = __shfl_sync(full, vv, (lrr + 1) & 31);
                    k1 = (lrr + 1 < cc) ? k1n : mna;
                } else {
                    // sh reached 0 with cc>32: all matching keys identical
                    k0 = scr[0];
                    k1 = (lrr + 1 < cc) ? k0 : mna;
                }
            }
            v0 = key2f(k0);
            if (need1) v1 = key2f(k1);
        } else {
            const unsigned* row = sm + ts * RS;
            v0 = key2f(generic_select_row(row, lane, R0[v]));
            if (need1) v1 = key2f(generic_select_row(row, lane, R0[v] + 1));
        }
        if (lane == 0) {
            float* qo = qout + ts * 8;
            if (v == 0) { qo[0] = v0; qo[1] = v1; }
            else if (v == 1) { qo[2] = v0; }
            else { qo[3] = v0; qo[4] = v1; }
        }
    }
    __syncthreads();

    // ---- phase 4: finalize (warp 0, lanes 0..3 -> one series each) ----
    if (w == 0 && lane < SPB) {
        int ts = lane;
        const unsigned* r0 = sm + REC_OFF + (2 * ts) * 16;
        const unsigned* r1 = r0 + 16;
        float ts1 = __uint_as_float(r0[0]) + __uint_as_float(r1[0]);
        float ts2 = __uint_as_float(r0[1]) + __uint_as_float(r1[1]);
        float ts3 = __uint_as_float(r0[2]) + __uint_as_float(r1[2]);
        float ts4 = __uint_as_float(r0[3]) + __uint_as_float(r1[3]);
        float tmn = fminf(__uint_as_float(r0[4]), __uint_as_float(r1[4]));
        float tmx = fmaxf(__uint_as_float(r0[5]), __uint_as_float(r1[5]));
        const float* qo = qout + ts * 8;

        const float n = 2048.f;
        float mean = ts1 / n;
        float m2 = ts2 / n, m3 = ts3 / n, m4 = ts4 / n;
        float varp = m2 - mean * mean;
        float var1 = varp * (n / (n - 1.f));
        float sd = sqrtf(var1);
        float mu2 = mean * mean;
        float m4c = m4 - 4.f * mean * m3 + 6.f * mu2 * m2 - 3.f * mu2 * mu2;
        float kurt = m4c / (var1 * var1) - 3.f;
        float q25 = 0.25f * qo[0] + 0.75f * qo[1];   // pos 511.75
        float med = qo[2];                            // pos 1023
        float q75 = 0.75f * qo[3] + 0.25f * qo[4];   // pos 1535.25

        int jg = part * SPB + ts;                     // 0..23
        int base = (jg < 12) ? 0 : 8;
        int col  = (jg < 12) ? jg : (jg - 12);
        float* o = g_stat2 + ((size_t)bc * 16 + base) * 12 + col;
        o[0 * 12] = tmx;
        o[1 * 12] = q25;
        o[2 * 12] = med;
        o[3 * 12] = q75;
        o[4 * 12] = mean;
        o[5 * 12] = sd;
        o[6 * 12] = tmx - tmn;
        o[7 * 12] = kurt;
    }

    // ---- weff tail folded in: blocks 0..119, threads 0..127 ----
    if (blk < 120 && tid < 128) {
        int idx = blk * 128 + tid;                    // 0 .. 15359
        int j   = idx % 12;
        int sx  = (idx / 12) & 15;
        int cx  = (idx / 192) & 15;
        int cls = idx / 3072;
        float a = 0.f;
#pragma unroll 8
        for (int e = 0; e < 64; e++)
            a += __ldg(&Wl[cls * 1024 + e * 16 + sx]) *
                 __ldg(&W2[(e * 16 + cx) * 12 + j]);
        g_weff[idx] = a;
    }
}

// ---------------------------------------------------------------------------
// Kernel B: logits[b,cls] = dot(stat2[b], weff[cls]) + sum b2*Wl + bl
// ---------------------------------------------------------------------------
__global__ __launch_bounds__(128)
void logits_kernel(const float* __restrict__ Wl, const float* __restrict__ b2,
                   const float* __restrict__ bl, float* __restrict__ out) {
    __shared__ float part[4];
    const unsigned full = 0xffffffffu;
    int blk = blockIdx.x;
    int b = blk / 5, cls = blk - b * 5;
    int tid = threadIdx.x;
    const float* st = g_stat2 + (size_t)b * 3072;
    const float* wf = g_weff + (size_t)cls * 3072;
    float a = 0.f;
    for (int i = tid; i < 3072; i += 128) a += st[i] * wf[i];
    for (int k = tid; k < 1024; k += 128)
        a += __ldg(&b2[k >> 4]) * __ldg(&Wl[cls * 1024 + k]);
#pragma unroll
    for (int d = 16; d; d >>= 1) a += __shfl_xor_sync(full, a, d);
    if ((tid & 31) == 0) part[tid >> 5] = a;
    __syncthreads();
    if (tid == 0)
        out[b * 5 + cls] = part[0] + part[1] + part[2] + part[3] + bl[cls];
}

// ---------------------------------------------------------------------------
extern "C" void kernel_launch(void* const* d_in, const int* in_sizes, int n_in,
                              void* d_out, int out_size) {
    const float* features = (const float*)d_in[0];
    // d_in[1]=W1, d_in[2]=b1 : dead in the reference (result discarded)
    const float* W2 = (const float*)d_in[3];
    const float* b2 = (const float*)d_in[4];
    const float* Wl = (const float*)d_in[5];
    const float* bl = (const float*)d_in[6];
    float* out = (float*)d_out;

    cudaFuncSetAttribute(stats_kernel,
                         cudaFuncAttributeMaxDynamicSharedMemorySize,
                         SMEM_BYTES);

    stats_kernel<<<BB * CC * NPARTS, NT, SMEM_BYTES>>>(features, W2, Wl);
    logits_kernel<<<BB * 5, 128>>>(Wl, b2, bl, out);
}